// round 13
// baseline (speedup 1.0000x reference)
#include <cuda_runtime.h>
#include <stdint.h>

#define NB   256
#define NK   64
#define NL   32
#define NM   (NK * NL)            // 2048 rows per (side, batch) block
#define NTOT (2 * NB * NM)        // 1,048,576 output rows
#define SENT 32
#define TBL  4096
#define TMASK 4095u
#define EMPTYV 0xFFFFFFFFu
#define NODE_MASK 0x1FFFFu        // node ids < 100000 < 2^17
#define VALIDF 0x80000000u

#define CTAS 592                  // 4 * 148 SMs: one co-resident wave
#define RPC  1772                 // ceil(NTOT / CTAS); multiple of 4
#define NTABS 512                 // one builder CTA per (side, batch) table

// first-seen tables (8 MB, L2-resident)
__device__ uint32_t g_tab[NTABS * TBL];
// monotonic per-CTA epoch slots: +1 per slot per run -> replay-safe
__device__ unsigned g_ready[CTAS];

__device__ __forceinline__ int ht_finish_g(const uint32_t* __restrict__ tab,
                                           uint32_t node, uint32_t h, uint32_t cur) {
    // `cur` is the already-loaded first probe at slot h
    #pragma unroll 1
    for (;;) {
        if (cur == EMPTYV) return SENT;
        if ((cur & NODE_MASK) == node) return (int)(cur >> 17);
        h = (h + 1) & TMASK;
        cur = __ldg(&tab[h]);
    }
}

__global__ __launch_bounds__(512, 4) void wpe_kernel(
    const int* __restrict__ src_walks, const int* __restrict__ tgt_walks,
    const int* __restrict__ src_lens,  const int* __restrict__ tgt_lens,
    const float* __restrict__ own_emb, const float* __restrict__ cross_emb,
    float* __restrict__ out)
{
    __shared__ uint32_t tab[TBL];         // 16 KB (builders only)
    __shared__ uint32_t s_info[RPC + 4];  // 7 KB: node|valid -> code|valid

    const int bid = blockIdx.x;
    const int tid = threadIdx.x;
    const int warp = tid >> 5, lane = tid & 31;
    const int half = lane >> 4, col = lane & 15;

    long r0 = (long)bid * RPC;
    long r1 = r0 + RPC; if (r1 > NTOT) r1 = NTOT;
    const int cnt = (int)(r1 - r0);      // always a multiple of 4

    __shared__ unsigned sh_E;

    // ── stage 1: builders make ONE (side,batch) table ──
    if (bid < NTABS) {
        const int s = bid >> 8, b = bid & (NB - 1);
        const int* w  = (s == 0 ? src_walks : tgt_walks) + b * NM;
        const int* ln = (s == 0 ? src_lens  : tgt_lens)  + b * NK;

        {   // vector init
            uint4* t4 = (uint4*)tab;
            const uint4 e4 = make_uint4(EMPTYV, EMPTYV, EMPTYV, EMPTYV);
            t4[tid] = e4; t4[tid + 512] = e4;
        }
        __syncthreads();

        {   // one int4 walk load -> 4 inserts (same 32-row, same len)
            const int m0 = tid * 4;
            const int4 wv = *(const int4*)(w + m0);
            const int len = ln[m0 >> 5];
            const int l0 = m0 & (NL - 1);
            const int nodes[4] = { wv.x, wv.y, wv.z, wv.w };
            #pragma unroll
            for (int j = 0; j < 4; j++) {
                int node = nodes[j];
                int l = l0 + j;
                if (node != 0 && l < len) {
                    uint32_t packed = ((uint32_t)l << 17) | (uint32_t)node;
                    uint32_t h = ((uint32_t)node * 2654435761u) & TMASK;
                    #pragma unroll 1
                    for (;;) {
                        uint32_t cur = tab[h];
                        if (cur == EMPTYV) {
                            cur = atomicCAS(&tab[h], EMPTYV, packed);
                            if (cur == EMPTYV) break;
                        }
                        if ((cur & NODE_MASK) == (uint32_t)node) {
                            atomicMin(&tab[h], packed);   // same key: packed-min == pos-min
                            break;
                        }
                        h = (h + 1) & TMASK;
                    }
                }
            }
        }
        __syncthreads();

        // ── stage 1b: OVERLAP — warps 0..7 dump table, warps 8..15 prepass ──
        if (warp < 8) {
            uint4* dst = (uint4*)(g_tab + (size_t)bid * TBL);
            const uint4* srcv = (const uint4*)tab;
            #pragma unroll
            for (int i = tid; i < TBL / 4; i += 256) dst[i] = srcv[i];
        } else {
            const int st = tid - 256;
            for (int i0 = st * 4; i0 < cnt; i0 += 256 * 4) {
                long r = r0 + i0;
                const int ss = (int)(r >> 19);
                const int bb = (int)((r >> 11) & (NB - 1));
                const int m0 = (int)(r & (NM - 1));          // multiple of 4
                const int* ww  = (ss == 0 ? src_walks : tgt_walks) + bb * NM;
                const int* lln = (ss == 0 ? src_lens  : tgt_lens)  + bb * NK;
                const int4 wv = *(const int4*)(ww + m0);
                const int len = lln[m0 >> 5];
                const int l0 = m0 & (NL - 1);
                const int nodes[4] = { wv.x, wv.y, wv.z, wv.w };
                #pragma unroll
                for (int j = 0; j < 4; j++)
                    s_info[i0 + j] = (nodes[j] != 0 && (l0 + j) < len)
                                   ? ((uint32_t)nodes[j] | VALIDF) : 0u;
            }
        }
        __syncthreads();
        if (tid == 0) {
            __threadfence();                               // publish table dump
            sh_E = atomicAdd(&g_ready[bid], 1u) + 1u;      // learn run epoch
        }
    } else {
        // non-builder: prepass with all 512 threads, int4 loads
        for (int i0 = tid * 4; i0 < cnt; i0 += 512 * 4) {
            long r = r0 + i0;
            const int ss = (int)(r >> 19);
            const int bb = (int)((r >> 11) & (NB - 1));
            const int m0 = (int)(r & (NM - 1));
            const int* ww  = (ss == 0 ? src_walks : tgt_walks) + bb * NM;
            const int* lln = (ss == 0 ? src_lens  : tgt_lens)  + bb * NK;
            const int4 wv = *(const int4*)(ww + m0);
            const int len = lln[m0 >> 5];
            const int l0 = m0 & (NL - 1);
            const int nodes[4] = { wv.x, wv.y, wv.z, wv.w };
            #pragma unroll
            for (int j = 0; j < 4; j++)
                s_info[i0 + j] = (nodes[j] != 0 && (l0 + j) < len)
                               ? ((uint32_t)nodes[j] | VALIDF) : 0u;
        }
        if (tid == 0) sh_E = atomicAdd(&g_ready[bid], 1u) + 1u;
    }
    __syncthreads();
    const unsigned E = sh_E;

    // ── stage 3: emit zeros for invalid rows NOW (overlaps builder latency) ──
    float4* out4 = (float4*)out;
    const float4 z4 = make_float4(0.f, 0.f, 0.f, 0.f);
    {
        int i = warp;
        for (; i + 64 <= cnt; i += 64) {           // 4-deep batches for store MLP
            uint32_t p[4];
            #pragma unroll
            for (int j = 0; j < 4; j++) p[j] = s_info[i + j * 16];
            #pragma unroll
            for (int j = 0; j < 4; j++)
                if (!(p[j] & VALIDF))
                    __stcs(&out4[(size_t)(r0 + i + j * 16) * 32 + lane], z4);
        }
        for (; i < cnt; i += 16)
            if (!(s_info[i] & VALIDF))
                __stcs(&out4[(size_t)(r0 + i) * 32 + lane], z4);
    }

    // ── stage 4: wait for the <=2 batches' tables (usually already done) ──
    if (tid == 0) {
        const int b0 = (int)((r0 >> 11) & (NB - 1));
        const int b1 = (int)(((r1 - 1) >> 11) & (NB - 1));
        while (*(volatile unsigned*)&g_ready[b0]       < E) __nanosleep(32);
        while (*(volatile unsigned*)&g_ready[256 + b0] < E) __nanosleep(32);
        if (b1 != b0) {
            while (*(volatile unsigned*)&g_ready[b1]       < E) __nanosleep(32);
            while (*(volatile unsigned*)&g_ready[256 + b1] < E) __nanosleep(32);
        }
        __threadfence();                                   // acquire tables
    }
    __syncthreads();

    // ── stage 5: resolve valid rows, 4 rows/thread with batched first probes ──
    for (int i0 = tid * 4; i0 < cnt; i0 += 512 * 4) {
        long r = r0 + i0;
        const int s = (int)(r >> 19);
        const int b = (int)((r >> 11) & (NB - 1));
        const uint32_t* mytab = g_tab + ((size_t)(s       * NB + b)) * TBL;
        const uint32_t* xtab  = g_tab + ((size_t)((s ^ 1) * NB + b)) * TBL;

        uint32_t info[4];
        #pragma unroll
        for (int j = 0; j < 4; j++) info[j] = s_info[i0 + j];

        uint32_t hm[4], hx[4], cm[4], cx[4];
        #pragma unroll
        for (int j = 0; j < 4; j++) {                      // 8 independent probes
            uint32_t node = info[j] & NODE_MASK;
            uint32_t h = (node * 2654435761u) & TMASK;
            hm[j] = h; hx[j] = h;
            if (info[j] & VALIDF) {
                cm[j] = __ldg(&mytab[h]);
                cx[j] = __ldg(&xtab[h]);
            }
        }
        #pragma unroll
        for (int j = 0; j < 4; j++) {
            if (info[j] & VALIDF) {
                uint32_t node = info[j] & NODE_MASK;
                int own   = ht_finish_g(mytab, node, hm[j], cm[j]);
                int cross = ht_finish_g(xtab,  node, hx[j], cx[j]);
                s_info[i0 + j] = (uint32_t)(own | (cross << 6)) | VALIDF;
            }
        }
    }
    __syncthreads();

    // ── stage 6: emit valid rows (4-deep batching for store MLP) ──
    const float4* oe = (const float4*)own_emb;     // 33 rows x 16 float4
    const float4* ce = (const float4*)cross_emb;

    int i = warp;
    for (; i + 64 <= cnt; i += 64) {
        uint32_t p[4];
        #pragma unroll
        for (int j = 0; j < 4; j++) p[j] = s_info[i + j * 16];
        #pragma unroll
        for (int j = 0; j < 4; j++) {
            if (p[j] & VALIDF) {
                int own   = p[j] & 63;
                int cross = (p[j] >> 6) & 63;
                float4 v = half ? __ldg(&ce[cross * 16 + col])
                                : __ldg(&oe[own   * 16 + col]);
                __stcs(&out4[(size_t)(r0 + i + j * 16) * 32 + lane], v);
            }
        }
    }
    for (; i < cnt; i += 16) {
        uint32_t p = s_info[i];
        if (p & VALIDF) {
            int own   = p & 63;
            int cross = (p >> 6) & 63;
            float4 v = half ? __ldg(&ce[cross * 16 + col])
                            : __ldg(&oe[own   * 16 + col]);
            __stcs(&out4[(size_t)(r0 + i) * 32 + lane], v);
        }
    }
}

extern "C" void kernel_launch(void* const* d_in, const int* in_sizes, int n_in,
                              void* d_out, int out_size) {
    (void)in_sizes; (void)n_in; (void)out_size;
    wpe_kernel<<<CTAS, 512>>>(
        (const int*)d_in[0], (const int*)d_in[1],
        (const int*)d_in[2], (const int*)d_in[3],
        (const float*)d_in[4], (const float*)d_in[5],
        (float*)d_out);
}

// round 16
// speedup vs baseline: 1.3484x; 1.3484x over previous
#include <cuda_runtime.h>
#include <stdint.h>

#define NB   256
#define NK   64
#define NL   32
#define NM   (NK * NL)            // 2048 rows per (side, batch) block
#define NTOT (2 * NB * NM)        // 1,048,576 output rows
#define SENT 32
#define TBL  4096
#define TMASK 4095u
#define EMPTYV 0xFFFFFFFFu
#define NODE_MASK 0x1FFFFu        // node ids < 100000 < 2^17
#define VALIDF 0x80000000u

#define CTAS 592                  // 4 * 148 SMs: one co-resident wave
#define RPC  1772                 // ceil(NTOT / CTAS); slice spans <= 2 blocks
#define NTABS 512                 // one builder CTA per (side, batch) table

// first-seen tables (8 MB, L2-resident)
__device__ uint32_t g_tab[NTABS * TBL];
// monotonic per-CTA epoch slots: +1 per slot per run -> replay-safe
__device__ unsigned g_ready[CTAS];

__device__ __forceinline__ int ht_finish_g(const uint32_t* __restrict__ tab,
                                           uint32_t node, uint32_t h, uint32_t cur) {
    // `cur` is the already-loaded probe at slot h
    #pragma unroll 1
    for (;;) {
        if (cur == EMPTYV) return SENT;
        if ((cur & NODE_MASK) == node) return (int)(cur >> 17);
        h = (h + 1) & TMASK;
        cur = __ldg(&tab[h]);
    }
}

__global__ __launch_bounds__(512, 4) void wpe_kernel(
    const int* __restrict__ src_walks, const int* __restrict__ tgt_walks,
    const int* __restrict__ src_lens,  const int* __restrict__ tgt_lens,
    const float* __restrict__ own_emb, const float* __restrict__ cross_emb,
    float* __restrict__ out)
{
    __shared__ uint32_t tab[TBL];         // 16 KB (builders only)
    __shared__ uint32_t s_info[RPC + 4];  // 7 KB: node|valid -> code|valid

    const int bid = blockIdx.x;
    const int tid = threadIdx.x;
    const int warp = tid >> 5, lane = tid & 31;
    const int half = lane >> 4, col = lane & 15;

    long r0 = (long)bid * RPC;
    long r1 = r0 + RPC; if (r1 > NTOT) r1 = NTOT;
    const int cnt = (int)(r1 - r0);

    __shared__ unsigned sh_E;

    // ── stage 1: builders make ONE (side,batch) table ──
    if (bid < NTABS) {
        const int s = bid >> 8, b = bid & (NB - 1);
        const int* w  = (s == 0 ? src_walks : tgt_walks) + b * NM;
        const int* ln = (s == 0 ? src_lens  : tgt_lens)  + b * NK;

        for (int i = tid; i < TBL; i += 512) tab[i] = EMPTYV;
        __syncthreads();

        #pragma unroll
        for (int r = 0; r < NM / 512; r++) {
            int m = tid + r * 512;
            int node = w[m];
            int l = m & (NL - 1);
            if (node != 0 && l < ln[m >> 5]) {
                uint32_t packed = ((uint32_t)l << 17) | (uint32_t)node;
                uint32_t h = ((uint32_t)node * 2654435761u) & TMASK;
                #pragma unroll 1
                for (;;) {
                    uint32_t cur = tab[h];
                    if (cur == EMPTYV) {
                        cur = atomicCAS(&tab[h], EMPTYV, packed);
                        if (cur == EMPTYV) break;
                    }
                    if ((cur & NODE_MASK) == (uint32_t)node) {
                        atomicMin(&tab[h], packed);   // same key: packed-min == pos-min
                        break;
                    }
                    h = (h + 1) & TMASK;
                }
            }
        }
        __syncthreads();

        // ── stage 1b: OVERLAP — warps 0..7 dump table, warps 8..15 do prepass ──
        if (warp < 8) {
            uint4* dst = (uint4*)(g_tab + (size_t)bid * TBL);
            const uint4* srcv = (const uint4*)tab;
            #pragma unroll
            for (int i = tid; i < TBL / 4; i += 256) dst[i] = srcv[i];
        } else {
            const int st = tid - 256;
            for (int i = st; i < cnt; i += 256) {
                long r = r0 + i;
                const int ss = (int)(r >> 19);
                const int bb = (int)((r >> 11) & (NB - 1));
                const int m  = (int)(r & (NM - 1));
                const int* ww  = (ss == 0 ? src_walks : tgt_walks) + bb * NM;
                const int* lln = (ss == 0 ? src_lens  : tgt_lens)  + bb * NK;
                int node = ww[m];
                int l = m & (NL - 1);
                s_info[i] = (node != 0 && l < lln[m >> 5]) ? ((uint32_t)node | VALIDF) : 0u;
            }
        }
        __syncthreads();
        if (tid == 0) {
            __threadfence();                               // publish table dump
            sh_E = atomicAdd(&g_ready[bid], 1u) + 1u;      // learn run epoch
        }
    } else {
        // non-builder: prepass with all 512 threads
        for (int i = tid; i < cnt; i += 512) {
            long r = r0 + i;
            const int ss = (int)(r >> 19);
            const int bb = (int)((r >> 11) & (NB - 1));
            const int m  = (int)(r & (NM - 1));
            const int* ww  = (ss == 0 ? src_walks : tgt_walks) + bb * NM;
            const int* lln = (ss == 0 ? src_lens  : tgt_lens)  + bb * NK;
            int node = ww[m];
            int l = m & (NL - 1);
            s_info[i] = (node != 0 && l < lln[m >> 5]) ? ((uint32_t)node | VALIDF) : 0u;
        }
        if (tid == 0) sh_E = atomicAdd(&g_ready[bid], 1u) + 1u;
    }
    __syncthreads();
    const unsigned E = sh_E;

    // ── stage 3: emit zeros for invalid rows NOW (overlaps builder latency) ──
    float4* out4 = (float4*)out;
    const float4 z4 = make_float4(0.f, 0.f, 0.f, 0.f);
    {
        int i = warp;
        for (; i + 64 <= cnt; i += 64) {           // 4-deep batches for store MLP
            uint32_t p[4];
            #pragma unroll
            for (int j = 0; j < 4; j++) p[j] = s_info[i + j * 16];
            #pragma unroll
            for (int j = 0; j < 4; j++)
                if (!(p[j] & VALIDF))
                    __stcs(&out4[(size_t)(r0 + i + j * 16) * 32 + lane], z4);
        }
        for (; i < cnt; i += 16)
            if (!(s_info[i] & VALIDF))
                __stcs(&out4[(size_t)(r0 + i) * 32 + lane], z4);
    }

    // ── stage 4: wait for the <=2 batches' tables (usually already done) ──
    if (tid == 0) {
        const int b0 = (int)((r0 >> 11) & (NB - 1));
        const int b1 = (int)(((r1 - 1) >> 11) & (NB - 1));
        while (*(volatile unsigned*)&g_ready[b0]       < E) __nanosleep(32);
        while (*(volatile unsigned*)&g_ready[256 + b0] < E) __nanosleep(32);
        if (b1 != b0) {
            while (*(volatile unsigned*)&g_ready[b1]       < E) __nanosleep(32);
            while (*(volatile unsigned*)&g_ready[256 + b1] < E) __nanosleep(32);
        }
        __threadfence();                                   // acquire tables
    }
    __syncthreads();

    // ── stage 5: resolve valid rows; both first probes issued back-to-back ──
    for (int i = tid; i < cnt; i += 512) {
        uint32_t info = s_info[i];
        if (info & VALIDF) {
            long r = r0 + i;
            const int s = (int)(r >> 19);
            const int b = (int)((r >> 11) & (NB - 1));
            uint32_t node = info & NODE_MASK;
            const uint32_t* mytab = g_tab + ((size_t)(s       * NB + b)) * TBL;
            const uint32_t* xtab  = g_tab + ((size_t)((s ^ 1) * NB + b)) * TBL;
            uint32_t h = (node * 2654435761u) & TMASK;
            uint32_t cm = __ldg(&mytab[h]);        // two independent probes in flight
            uint32_t cx = __ldg(&xtab[h]);
            int own   = ht_finish_g(mytab, node, h, cm);
            int cross = ht_finish_g(xtab,  node, h, cx);
            s_info[i] = (uint32_t)(own | (cross << 6)) | VALIDF;
        }
    }
    __syncthreads();

    // ── stage 6: emit valid rows (4-deep batching for store MLP) ──
    const float4* oe = (const float4*)own_emb;     // 33 rows x 16 float4
    const float4* ce = (const float4*)cross_emb;

    int i = warp;
    for (; i + 64 <= cnt; i += 64) {
        uint32_t p[4];
        #pragma unroll
        for (int j = 0; j < 4; j++) p[j] = s_info[i + j * 16];
        #pragma unroll
        for (int j = 0; j < 4; j++) {
            if (p[j] & VALIDF) {
                int own   = p[j] & 63;
                int cross = (p[j] >> 6) & 63;
                float4 v = half ? __ldg(&ce[cross * 16 + col])
                                : __ldg(&oe[own   * 16 + col]);
                __stcs(&out4[(size_t)(r0 + i + j * 16) * 32 + lane], v);
            }
        }
    }
    for (; i < cnt; i += 16) {
        uint32_t p = s_info[i];
        if (p & VALIDF) {
            int own   = p & 63;
            int cross = (p >> 6) & 63;
            float4 v = half ? __ldg(&ce[cross * 16 + col])
                            : __ldg(&oe[own   * 16 + col]);
            __stcs(&out4[(size_t)(r0 + i) * 32 + lane], v);
        }
    }
}

extern "C" void kernel_launch(void* const* d_in, const int* in_sizes, int n_in,
                              void* d_out, int out_size) {
    (void)in_sizes; (void)n_in; (void)out_size;
    wpe_kernel<<<CTAS, 512>>>(
        (const int*)d_in[0], (const int*)d_in[1],
        (const int*)d_in[2], (const int*)d_in[3],
        (const float*)d_in[4], (const float*)d_in[5],
        (float*)d_out);
}